// round 1
// baseline (speedup 1.0000x reference)
#include <cuda_runtime.h>
#include <cstdint>

// CTRNN: h_{t+1} = 0.8*h_t + 0.2*tanh(x_t@W_in^T + b + h_t@W_hh^T)
// T=1000, B=256, I=128, N=512.
//
// 16 clusters x 8 CTAs (persistent, 1 CTA/SM). Cluster = 16 batch rows.
// CTA rank = 64 output columns, W_hh slice resident in smem.
// Per-step h exchange through L2 (double-buffered __device__ buffer),
// synchronized with cluster.sync only (batch rows are independent).

#define T_STEPS 1000
#define B 256
#define I 128
#define N 512
#define BN (B * N)

#define WHH_PITCH 516                      // 512 + 4 pad -> conflict-free LDS.128
#define SMEM_FLOATS (64 * WHH_PITCH + 16 * 512 + 8192 + 64)
#define SMEM_BYTES (SMEM_FLOATS * 4)       // 197,888 bytes

__device__ float g_h[2][BN];               // h exchange buffers (L2-resident, 1MB)

__device__ __forceinline__ void dfma2(unsigned long long &acc,
                                      unsigned long long a,
                                      unsigned long long b) {
    asm("fma.rn.f32x2 %0, %1, %2, %0;" : "+l"(acc) : "l"(a), "l"(b));
}

__device__ __forceinline__ float2 unpk(unsigned long long v) {
    float2 f;
    asm("mov.b64 {%0, %1}, %2;" : "=f"(f.x), "=f"(f.y) : "l"(v));
    return f;
}

__device__ __forceinline__ void cluster_barrier() {
    asm volatile("barrier.cluster.arrive.aligned;" ::: "memory");
    asm volatile("barrier.cluster.wait.aligned;" ::: "memory");
}

extern "C" __global__ void __launch_bounds__(256, 1) __cluster_dims__(8, 1, 1)
ctrnn_kernel(const float* __restrict__ x,
             const float* __restrict__ h0,
             const float* __restrict__ W_in,
             const float* __restrict__ b_in,
             const float* __restrict__ W_hh,
             float* __restrict__ out) {
    extern __shared__ float S[];
    float* Whh_s = S;                          // [64][516]
    float* h_s   = S + 64 * WHH_PITCH;         // [16][512]
    float* xred  = h_s + 16 * 512;             // union: x [16][128] / red [8][16][64]
    float* b_s   = xred + 8192;                // [64]

    const int tid  = threadIdx.x;
    const int g    = tid >> 5;                 // warp id = k-group (0..7)
    const int lane = tid & 31;
    const int cid  = blockIdx.x >> 3;          // cluster id (0..15) -> batch group
    const int rank = blockIdx.x & 7;           // rank in cluster -> column group
    const int rows0 = cid * 16;
    const int cols0 = rank * 64;
    const int c0 = lane, c1 = lane + 32;

    // ---- one-time init: stage W_hh slice + bias into smem, W_in slice into regs ----
    for (int idx = tid; idx < 64 * 128; idx += 256) {
        int c = idx >> 7, kq = idx & 127;
        float4 v = *(const float4*)(W_hh + (size_t)(cols0 + c) * N + kq * 4);
        *(float4*)(Whh_s + c * WHH_PITCH + kq * 4) = v;
    }
    if (tid < 64) b_s[tid] = b_in[cols0 + tid];

    unsigned long long win0[8], win1[8];       // W_in[c][g*16 .. g*16+15] as f32x2 pairs
    {
        const unsigned long long* p0 =
            (const unsigned long long*)(W_in + (size_t)(cols0 + c0) * I + g * 16);
        const unsigned long long* p1 =
            (const unsigned long long*)(W_in + (size_t)(cols0 + c1) * I + g * 16);
#pragma unroll
        for (int m = 0; m < 8; m++) { win0[m] = p0[m]; win1[m] = p1[m]; }
    }

    // init h exchange buffer with h0 (this CTA's 16x64 tile)
    for (int o = tid; o < 1024; o += 256) {
        int r = o >> 6, c = o & 63;
        int gidx = (rows0 + r) * N + cols0 + c;
        g_h[0][gidx] = h0[gidx];
    }
    __threadfence();
    cluster_barrier();

    int p = 0;
    for (int t = 0; t < T_STEPS; t++) {
        // ---- stage h_t (full 16x512) and x_t (16x128) ----
        const float4* hsrc = (const float4*)(g_h[p] + rows0 * N);
#pragma unroll
        for (int q = 0; q < 8; q++)
            ((float4*)h_s)[tid + q * 256] = __ldcg(hsrc + tid + q * 256);
        const float4* xsrc = (const float4*)(x + (size_t)t * B * I + rows0 * I);
        ((float4*)xred)[tid]       = __ldcs(xsrc + tid);
        ((float4*)xred)[tid + 256] = __ldcs(xsrc + tid + 256);
        __syncthreads();

        // ---- partial GEMM: this warp covers k in [g*64, g*64+64) of W_hh
        //      and i in [g*16, g*16+16) of W_in, for 16 rows x 2 cols ----
        unsigned long long a0[16], a1[16];
#pragma unroll
        for (int r = 0; r < 16; r++) { a0[r] = 0ULL; a1[r] = 0ULL; }

        {
            const ulonglong2* w0p = (const ulonglong2*)(Whh_s + c0 * WHH_PITCH + g * 64);
            const ulonglong2* w1p = (const ulonglong2*)(Whh_s + c1 * WHH_PITCH + g * 64);
            const float* hbase = h_s + g * 64;
#pragma unroll 4
            for (int m = 0; m < 16; m++) {
                ulonglong2 w0 = w0p[m], w1 = w1p[m];
                const float* hk = hbase + m * 4;
#pragma unroll
                for (int r = 0; r < 16; r++) {
                    ulonglong2 hv = *(const ulonglong2*)(hk + r * 512);
                    dfma2(a0[r], hv.x, w0.x); dfma2(a0[r], hv.y, w0.y);
                    dfma2(a1[r], hv.x, w1.x); dfma2(a1[r], hv.y, w1.y);
                }
            }
            const float* xbase = xred + g * 16;
#pragma unroll
            for (int m = 0; m < 4; m++) {
                const float* xk = xbase + m * 4;
#pragma unroll
                for (int r = 0; r < 16; r++) {
                    ulonglong2 xv = *(const ulonglong2*)(xk + r * 128);
                    dfma2(a0[r], xv.x, win0[2 * m]); dfma2(a0[r], xv.y, win0[2 * m + 1]);
                    dfma2(a1[r], xv.x, win1[2 * m]); dfma2(a1[r], xv.y, win1[2 * m + 1]);
                }
            }
        }
        __syncthreads();   // everyone done reading x tile before reusing as reduce buf

        // ---- dump per-warp partials (horizontal f32x2 sum) ----
#pragma unroll
        for (int r = 0; r < 16; r++) {
            float2 f0 = unpk(a0[r]);
            float2 f1 = unpk(a1[r]);
            xred[g * 1024 + r * 64 + c0] = f0.x + f0.y;
            xred[g * 1024 + r * 64 + c1] = f1.x + f1.y;
        }
        __syncthreads();

        // ---- reduce over 8 k-groups, activation, blend, store ----
        size_t outbase = (size_t)t * BN;
#pragma unroll
        for (int q = 0; q < 4; q++) {
            int o = tid + q * 256;
            int r = o >> 6, c = o & 63;
            float z = b_s[c];
#pragma unroll
            for (int gg = 0; gg < 8; gg++) z += xred[gg * 1024 + r * 64 + c];
            float hold = h_s[r * 512 + cols0 + c];
            float hv = hold * 0.8f + 0.2f * tanhf(z);
            int gidx = (rows0 + r) * N + cols0 + c;
            __stcg(&g_h[p ^ 1][gidx], hv);            // exchange buffer (L2)
            __stcs(&out[outbase + gidx], hv);          // streamed output
            if (t == T_STEPS - 1)
                __stcs(&out[(size_t)T_STEPS * BN + gidx], hv);  // final hidden
        }
        __threadfence();
        cluster_barrier();
        p ^= 1;
    }
}

extern "C" void kernel_launch(void* const* d_in, const int* in_sizes, int n_in,
                              void* d_out, int out_size) {
    const float* x    = (const float*)d_in[0];
    const float* h0   = (const float*)d_in[1];
    const float* W_in = (const float*)d_in[2];
    const float* b_in = (const float*)d_in[3];
    const float* W_hh = (const float*)d_in[4];
    float* out = (float*)d_out;

    cudaFuncSetAttribute(ctrnn_kernel,
                         cudaFuncAttributeMaxDynamicSharedMemorySize, SMEM_BYTES);
    ctrnn_kernel<<<128, 256, SMEM_BYTES>>>(x, h0, W_in, b_in, W_hh, out);
}

// round 3
// speedup vs baseline: 1.1070x; 1.1070x over previous
#include <cuda_runtime.h>
#include <cstdint>

// CTRNN: h_{t+1} = 0.8*h_t + 0.2*tanh(x_t@W_in^T + b + h_t@W_hh^T)
// T=1000, B=256, I=128, N=512.
//
// 16 clusters x 8 CTAs (persistent, 1 CTA/SM), 512 threads/CTA.
// Cluster = 16 batch rows. CTA rank = 64 output cols, W_hh slice in smem.
// Warp (rg,g): rows rg*8..rg*8+8, k-slice g (64 of W_hh + 16 of W_in).
// h exchanged via double-buffered L2 global; ordering via the RELEASE/ACQUIRE
// semantics of barrier.cluster.arrive/wait (no threadfence). Output stores
// are issued between arrive and wait so their latency hides in the barrier.

#define T_STEPS 1000
#define B 256
#define I 128
#define N 512
#define BN (B * N)

#define WHH_PITCH 516  // 129 float4s/row (odd) -> conflict-free LDS.128
#define S_WHH 0
#define S_H   (64 * WHH_PITCH)            // [16][512]
#define S_X   (S_H + 16 * 512)            // [16][128]
#define S_RED (S_X + 16 * 128)            // [8][16][64]
#define S_B   (S_RED + 8 * 16 * 64)       // [64]
#define SMEM_FLOATS (S_B + 64)
#define SMEM_BYTES (SMEM_FLOATS * 4)      // 206,080 bytes

__device__ float g_h[2][BN];              // h exchange buffers (L2-resident, 1MB)

__device__ __forceinline__ void dfma2(unsigned long long &acc,
                                      unsigned long long a,
                                      unsigned long long b) {
    asm("fma.rn.f32x2 %0, %1, %2, %0;" : "+l"(acc) : "l"(a), "l"(b));
}

__device__ __forceinline__ float2 unpk(unsigned long long v) {
    float2 f;
    asm("mov.b64 {%0, %1}, %2;" : "=f"(f.x), "=f"(f.y) : "l"(v));
    return f;
}

__device__ __forceinline__ void cluster_arrive() {  // release @ cluster scope
    asm volatile("barrier.cluster.arrive.aligned;" ::: "memory");
}
__device__ __forceinline__ void cluster_wait() {    // acquire @ cluster scope
    asm volatile("barrier.cluster.wait.aligned;" ::: "memory");
}

extern "C" __global__ void __launch_bounds__(512, 1) __cluster_dims__(8, 1, 1)
ctrnn_kernel(const float* __restrict__ x,
             const float* __restrict__ h0,
             const float* __restrict__ W_in,
             const float* __restrict__ b_in,
             const float* __restrict__ W_hh,
             float* __restrict__ out) {
    extern __shared__ float S[];
    float* Whh_s = S + S_WHH;
    float* h_s   = S + S_H;
    float* x_s   = S + S_X;
    float* red   = S + S_RED;
    float* b_s   = S + S_B;

    const int tid  = threadIdx.x;
    const int warp = tid >> 5;
    const int g    = warp & 7;            // k-group (0..7)
    const int rg   = warp >> 3;           // row-group (0..1)
    const int lane = tid & 31;
    const int cid  = blockIdx.x >> 3;     // cluster id -> batch group
    const int rank = blockIdx.x & 7;      // rank -> column group
    const int rows0 = cid * 16;
    const int cols0 = rank * 64;
    const int c0 = lane, c1 = lane + 32;

    // ---- one-time init: W_hh slice + bias into smem, W_in slice into regs ----
    for (int idx = tid; idx < 64 * 128; idx += 512) {
        int c = idx >> 7, kq = idx & 127;
        float4 v = *(const float4*)(W_hh + (size_t)(cols0 + c) * N + kq * 4);
        *(float4*)(Whh_s + c * WHH_PITCH + kq * 4) = v;
    }
    if (tid < 64) b_s[tid] = b_in[cols0 + tid];

    unsigned long long win0[8], win1[8];  // W_in[c][g*16 .. g*16+15] as f32x2 pairs
    {
        const unsigned long long* p0 =
            (const unsigned long long*)(W_in + (size_t)(cols0 + c0) * I + g * 16);
        const unsigned long long* p1 =
            (const unsigned long long*)(W_in + (size_t)(cols0 + c1) * I + g * 16);
#pragma unroll
        for (int m = 0; m < 8; m++) { win0[m] = p0[m]; win1[m] = p1[m]; }
    }

    // init h exchange buffer with h0 (this CTA's 16x64 tile)
#pragma unroll
    for (int q = 0; q < 2; q++) {
        int o = tid + q * 512;
        int r = o >> 6, c = o & 63;
        int gidx = (rows0 + r) * N + cols0 + c;
        g_h[0][gidx] = h0[gidx];
    }
    // prefetch x_0 (1 float4/thread)
    float4 xr = __ldcs((const float4*)(x + (size_t)rows0 * I) + tid);

    cluster_arrive();
    cluster_wait();

    int p = 0;
    for (int t = 0; t < T_STEPS; t++) {
        // ---- stage x_t (from prefetch regs) and h_t (full 16x512 via L2) ----
        ((float4*)x_s)[tid] = xr;
        const float4* hsrc = (const float4*)(g_h[p] + rows0 * N);
#pragma unroll
        for (int q = 0; q < 4; q++)
            ((float4*)h_s)[tid + q * 512] = __ldcg(hsrc + tid + q * 512);
        __syncthreads();

        // prefetch x_{t+1} (off critical path; drains during GEMM)
        if (t + 1 < T_STEPS)
            xr = __ldcs((const float4*)(x + (size_t)(t + 1) * B * I +
                                        (size_t)rows0 * I) + tid);

        // ---- partial GEMM: rows rg*8..+8, cols c0/c1, k-slice g ----
        unsigned long long a0[8], a1[8];
#pragma unroll
        for (int r = 0; r < 8; r++) { a0[r] = 0ULL; a1[r] = 0ULL; }
        {
            const ulonglong2* w0p = (const ulonglong2*)(Whh_s + c0 * WHH_PITCH + g * 64);
            const ulonglong2* w1p = (const ulonglong2*)(Whh_s + c1 * WHH_PITCH + g * 64);
            const float* hbase = h_s + (rg * 8) * 512 + g * 64;
#pragma unroll 4
            for (int m = 0; m < 16; m++) {
                ulonglong2 w0 = w0p[m], w1 = w1p[m];
                const float* hk = hbase + m * 4;
#pragma unroll
                for (int r = 0; r < 8; r++) {
                    ulonglong2 hv = *(const ulonglong2*)(hk + r * 512);
                    dfma2(a0[r], hv.x, w0.x); dfma2(a0[r], hv.y, w0.y);
                    dfma2(a1[r], hv.x, w1.x); dfma2(a1[r], hv.y, w1.y);
                }
            }
            const float* xbase = x_s + (rg * 8) * 128 + g * 16;
#pragma unroll
            for (int m = 0; m < 4; m++) {
                const float* xk = xbase + m * 4;
#pragma unroll
                for (int r = 0; r < 8; r++) {
                    ulonglong2 xv = *(const ulonglong2*)(xk + r * 128);
                    dfma2(a0[r], xv.x, win0[2 * m]); dfma2(a0[r], xv.y, win0[2 * m + 1]);
                    dfma2(a1[r], xv.x, win1[2 * m]); dfma2(a1[r], xv.y, win1[2 * m + 1]);
                }
            }
        }

        // ---- dump per-warp partials (dedicated buffer -> no pre-sync) ----
        {
            float* rd = red + g * 1024 + (rg * 8) * 64;
#pragma unroll
            for (int r = 0; r < 8; r++) {
                float2 f0 = unpk(a0[r]);
                float2 f1 = unpk(a1[r]);
                rd[r * 64 + c0] = f0.x + f0.y;
                rd[r * 64 + c1] = f1.x + f1.y;
            }
        }
        __syncthreads();

        // ---- reduce over 8 k-groups, activation, blend ----
        float hvq[2];
        int gidxq[2];
        size_t outbase = (size_t)t * BN;
#pragma unroll
        for (int q = 0; q < 2; q++) {
            int o = tid + q * 512;
            int r = o >> 6, c = o & 63;
            float z = b_s[c];
#pragma unroll
            for (int gg = 0; gg < 8; gg++) z += red[gg * 1024 + r * 64 + c];
            float hold = h_s[r * 512 + cols0 + c];
            float hv = hold * 0.8f + 0.2f * tanhf(z);
            int gidx = (rows0 + r) * N + cols0 + c;
            __stcg(&g_h[p ^ 1][gidx], hv);     // exchange buffer (L2)
            hvq[q] = hv; gidxq[q] = gidx;
        }

        // release: g_h stores ordered by arrive; out stores hide in the wait
        cluster_arrive();
#pragma unroll
        for (int q = 0; q < 2; q++) {
            __stcs(&out[outbase + gidxq[q]], hvq[q]);
            if (t == T_STEPS - 1)
                __stcs(&out[(size_t)T_STEPS * BN + gidxq[q]], hvq[q]);
        }
        cluster_wait();
        p ^= 1;
    }
}

extern "C" void kernel_launch(void* const* d_in, const int* in_sizes, int n_in,
                              void* d_out, int out_size) {
    const float* x    = (const float*)d_in[0];
    const float* h0   = (const float*)d_in[1];
    const float* W_in = (const float*)d_in[2];
    const float* b_in = (const float*)d_in[3];
    const float* W_hh = (const float*)d_in[4];
    float* out = (float*)d_out;

    cudaFuncSetAttribute(ctrnn_kernel,
                         cudaFuncAttributeMaxDynamicSharedMemorySize, SMEM_BYTES);
    ctrnn_kernel<<<128, 512, SMEM_BYTES>>>(x, h0, W_in, b_in, W_hh, out);
}

// round 5
// speedup vs baseline: 1.1394x; 1.0293x over previous
#include <cuda_runtime.h>
#include <cstdint>

// CTRNN: h_{t+1} = 0.8*h_t + 0.2*tanh(x_t@W_in^T + b + h_t@W_hh^T)
// T=1000, B=256, I=128, N=512.
//
// 16 clusters x 8 CTAs (persistent, 1 CTA/SM), 256 threads/CTA (8 warps).
// Cluster = 16 batch rows. CTA rank = 64 output cols, W_hh slice in smem.
// Warp g = k-group: 64 k of W_hh + 16 i of W_in, for all 16 rows x 2 cols/lane.
// 256 threads -> 255-reg ceiling: headroom to software-pipeline the LDS
// stream under the FFMA2 stream (round-3 bottleneck: 128-reg cap at 512
// threads starved load hoisting -> exposed LDS latency, fma pipe 19%).
// h exchanged via double-buffered L2 global; ordering via cluster barrier
// release/acquire. Output stores issued inside the arrive->wait window.

#define T_STEPS 1000
#define B 256
#define I 128
#define N 512
#define BN (B * N)

#define WHH_PITCH 516  // 129 float4s/row (odd) -> conflict-free LDS.128
#define S_WHH 0
#define S_H   (64 * WHH_PITCH)            // [16][512]
#define S_X   (S_H + 16 * 512)            // [16][128]
#define S_RED (S_X + 16 * 128)            // [8][16][64]
#define S_B   (S_RED + 8 * 16 * 64)       // [64]
#define SMEM_FLOATS (S_B + 64)
#define SMEM_BYTES (SMEM_FLOATS * 4)      // 206,080 bytes

__device__ float g_h[2][BN];              // h exchange buffers (L2-resident, 1MB)

__device__ __forceinline__ void dfma2(unsigned long long &acc,
                                      unsigned long long a,
                                      unsigned long long b) {
    asm("fma.rn.f32x2 %0, %1, %2, %0;" : "+l"(acc) : "l"(a), "l"(b));
}

__device__ __forceinline__ float2 unpk(unsigned long long v) {
    float2 f;
    asm("mov.b64 {%0, %1}, %2;" : "=f"(f.x), "=f"(f.y) : "l"(v));
    return f;
}

__device__ __forceinline__ void cluster_arrive() {  // release @ cluster scope
    asm volatile("barrier.cluster.arrive.aligned;" ::: "memory");
}
__device__ __forceinline__ void cluster_wait() {    // acquire @ cluster scope
    asm volatile("barrier.cluster.wait.aligned;" ::: "memory");
}

extern "C" __global__ void __launch_bounds__(256, 1) __cluster_dims__(8, 1, 1)
ctrnn_kernel(const float* __restrict__ x,
             const float* __restrict__ h0,
             const float* __restrict__ W_in,
             const float* __restrict__ b_in,
             const float* __restrict__ W_hh,
             float* __restrict__ out) {
    extern __shared__ float S[];
    float* Whh_s = S + S_WHH;
    float* h_s   = S + S_H;
    float* x_s   = S + S_X;
    float* red   = S + S_RED;
    float* b_s   = S + S_B;

    const int tid  = threadIdx.x;
    const int g    = tid >> 5;            // warp id = k-group (0..7)
    const int lane = tid & 31;
    const int cid  = blockIdx.x >> 3;     // cluster id -> batch group
    const int rank = blockIdx.x & 7;      // rank -> column group
    const int rows0 = cid * 16;
    const int cols0 = rank * 64;
    const int c0 = lane, c1 = lane + 32;

    // ---- one-time init: W_hh slice + bias into smem, W_in slice into regs ----
    for (int idx = tid; idx < 64 * 128; idx += 256) {
        int c = idx >> 7, kq = idx & 127;
        float4 v = *(const float4*)(W_hh + (size_t)(cols0 + c) * N + kq * 4);
        *(float4*)(Whh_s + c * WHH_PITCH + kq * 4) = v;
    }
    if (tid < 64) b_s[tid] = b_in[cols0 + tid];

    unsigned long long win0[8], win1[8];  // W_in[c][g*16 .. g*16+15] as f32x2 pairs
    {
        const unsigned long long* p0 =
            (const unsigned long long*)(W_in + (size_t)(cols0 + c0) * I + g * 16);
        const unsigned long long* p1 =
            (const unsigned long long*)(W_in + (size_t)(cols0 + c1) * I + g * 16);
#pragma unroll
        for (int m = 0; m < 8; m++) { win0[m] = p0[m]; win1[m] = p1[m]; }
    }

    // init h exchange buffer with h0 (this CTA's 16x64 tile)
#pragma unroll
    for (int q = 0; q < 4; q++) {
        int o = tid + q * 256;
        int r = o >> 6, c = o & 63;
        int gidx = (rows0 + r) * N + cols0 + c;
        g_h[0][gidx] = h0[gidx];
    }
    // prefetch x_0 (2 float4/thread)
    float4 xr0 = __ldcs((const float4*)(x + (size_t)rows0 * I) + tid);
    float4 xr1 = __ldcs((const float4*)(x + (size_t)rows0 * I) + tid + 256);

    cluster_arrive();
    cluster_wait();

    int p = 0;
    for (int t = 0; t < T_STEPS; t++) {
        // ---- stage x_t (from prefetch regs) and h_t (full 16x512 via L2) ----
        ((float4*)x_s)[tid]       = xr0;
        ((float4*)x_s)[tid + 256] = xr1;
        const float4* hsrc = (const float4*)(g_h[p] + rows0 * N);
#pragma unroll
        for (int q = 0; q < 8; q++)
            ((float4*)h_s)[tid + q * 256] = __ldcg(hsrc + tid + q * 256);
        __syncthreads();

        // prefetch x_{t+1} (off critical path; drains during GEMM)
        if (t + 1 < T_STEPS) {
            const float4* xn = (const float4*)(x + (size_t)(t + 1) * B * I +
                                               (size_t)rows0 * I);
            xr0 = __ldcs(xn + tid);
            xr1 = __ldcs(xn + tid + 256);
        }

        // ---- partial GEMM: 16 rows, cols c0/c1, k-slice g ----
        unsigned long long a0[16], a1[16];
#pragma unroll
        for (int r = 0; r < 16; r++) { a0[r] = 0ULL; a1[r] = 0ULL; }
        {
            const ulonglong2* w0p = (const ulonglong2*)(Whh_s + c0 * WHH_PITCH + g * 64);
            const ulonglong2* w1p = (const ulonglong2*)(Whh_s + c1 * WHH_PITCH + g * 64);
            const float* hbase = h_s + g * 64;

            // software-pipelined over m: W for m+1 prefetched during row block m
            ulonglong2 w0 = w0p[0], w1 = w1p[0];
#pragma unroll 2
            for (int m = 0; m < 16; m++) {
                ulonglong2 w0c = w0, w1c = w1;
                if (m < 15) { w0 = w0p[m + 1]; w1 = w1p[m + 1]; }
                const float* hk = hbase + m * 4;
#pragma unroll
                for (int r = 0; r < 16; r++) {
                    ulonglong2 hv = *(const ulonglong2*)(hk + r * 512);
                    dfma2(a0[r], hv.x, w0c.x); dfma2(a0[r], hv.y, w0c.y);
                    dfma2(a1[r], hv.x, w1c.x); dfma2(a1[r], hv.y, w1c.y);
                }
            }
            const float* xbase = x_s + g * 16;
#pragma unroll
            for (int m = 0; m < 4; m++) {
                const float* xk = xbase + m * 4;
#pragma unroll
                for (int r = 0; r < 16; r++) {
                    ulonglong2 xv = *(const ulonglong2*)(xk + r * 128);
                    dfma2(a0[r], xv.x, win0[2 * m]); dfma2(a0[r], xv.y, win0[2 * m + 1]);
                    dfma2(a1[r], xv.x, win1[2 * m]); dfma2(a1[r], xv.y, win1[2 * m + 1]);
                }
            }
        }

        // ---- dump per-warp partials (dedicated buffer -> no pre-sync) ----
        {
            float* rd = red + g * 1024;
#pragma unroll
            for (int r = 0; r < 16; r++) {
                float2 f0 = unpk(a0[r]);
                float2 f1 = unpk(a1[r]);
                rd[r * 64 + c0] = f0.x + f0.y;
                rd[r * 64 + c1] = f1.x + f1.y;
            }
        }
        __syncthreads();

        // ---- reduce over 8 k-groups, activation, blend ----
        float hvq[4];
        int gidxq[4];
        size_t outbase = (size_t)t * BN;
#pragma unroll
        for (int q = 0; q < 4; q++) {
            int o = tid + q * 256;
            int r = o >> 6, c = o & 63;
            float z = b_s[c];
#pragma unroll
            for (int gg = 0; gg < 8; gg++) z += red[gg * 1024 + r * 64 + c];
            float hold = h_s[r * 512 + cols0 + c];
            float hv = hold * 0.8f + 0.2f * tanhf(z);
            int gidx = (rows0 + r) * N + cols0 + c;
            __stcg(&g_h[p ^ 1][gidx], hv);     // exchange buffer (L2)
            hvq[q] = hv; gidxq[q] = gidx;
        }

        // release: g_h stores ordered by arrive; out stores hide in the wait
        cluster_arrive();
#pragma unroll
        for (int q = 0; q < 4; q++) {
            __stcs(&out[outbase + gidxq[q]], hvq[q]);
            if (t == T_STEPS - 1)
                __stcs(&out[(size_t)T_STEPS * BN + gidxq[q]], hvq[q]);
        }
        cluster_wait();
        p ^= 1;
    }
}

extern "C" void kernel_launch(void* const* d_in, const int* in_sizes, int n_in,
                              void* d_out, int out_size) {
    const float* x    = (const float*)d_in[0];
    const float* h0   = (const float*)d_in[1];
    const float* W_in = (const float*)d_in[2];
    const float* b_in = (const float*)d_in[3];
    const float* W_hh = (const float*)d_in[4];
    float* out = (float*)d_out;

    cudaFuncSetAttribute(ctrnn_kernel,
                         cudaFuncAttributeMaxDynamicSharedMemorySize, SMEM_BYTES);
    ctrnn_kernel<<<128, 256, SMEM_BYTES>>>(x, h0, W_in, b_in, W_hh, out);
}

// round 13
// speedup vs baseline: 1.3373x; 1.1737x over previous
#include <cuda_runtime.h>
#include <cuda_bf16.h>
#include <cstdint>

// CTRNN: h_{t+1} = 0.8h + 0.2 tanh([h|x_t] @ [W_hh|W_in]^T + b)
// T=1000, B=256, I=128, N=512, K = 640.
//
// Core: warp-level mma.sync m16n8k16 bf16 (legacy HMMA path; tcgen05 is not
// compilable here: harness PTX targets compute_103 without the 'a' feature).
// 16 clusters x 8 CTAs (persistent, 1/SM), 256 thr. Cluster = 16 batch rows,
// CTA = 64 output cols, warp = one n8 strip x full K (no k-reduce).
// W resident in smem as bf16 hi/lo (once). h|x exchanged via L2 as bf16
// hi/lo double buffer; 3-term split (AhiBhi + AhiBlo + AloBhi) ~ 2^-16 acc.
// Ordering via cluster barrier release/acquire (round-5 proven protocol).

#define T_STEPS 1000
#define BATCH 256
#define INPUT 128
#define NHID 512
#define BN (BATCH * NHID)
#define KTOT 640
#define APITCH 648            // bf16 elems per row; 1296B -> ldmatrix conflict-free

// smem byte offsets (all 16B aligned)
#define S_WH 0
#define S_WL (S_WH + 64 * APITCH * 2)     //  82944
#define S_AH (S_WL + 64 * APITCH * 2)     // 165888
#define S_AL (S_AH + 16 * APITCH * 2)     // 186624
#define S_HOLD (S_AL + 16 * APITCH * 2)   // 207360  fp32 h_old [16][64]
#define S_BIAS (S_HOLD + 16 * 64 * 4)     // 211456  fp32 [64]
#define SMEM_BYTES (S_BIAS + 256)         // 211712

__device__ __nv_bfloat16 g_hh[2][BATCH][KTOT];   // hi parts of [h | x_t]
__device__ __nv_bfloat16 g_hl[2][BATCH][KTOT];   // lo parts

__device__ __forceinline__ uint32_t smem_u32(const void* p) {
    uint32_t a;
    asm("{ .reg .u64 t; cvta.to.shared.u64 t, %1; cvt.u32.u64 %0, t; }"
        : "=r"(a) : "l"(p));
    return a;
}

__device__ __forceinline__ void cluster_arrive() {  // release @ cluster scope
    asm volatile("barrier.cluster.arrive.aligned;" ::: "memory");
}
__device__ __forceinline__ void cluster_wait() {    // acquire @ cluster scope
    asm volatile("barrier.cluster.wait.aligned;" ::: "memory");
}

__device__ __forceinline__ void ldsm4(uint32_t* r, uint32_t a) {
    asm volatile("ldmatrix.sync.aligned.m8n8.x4.shared.b16 {%0,%1,%2,%3}, [%4];"
                 : "=r"(r[0]), "=r"(r[1]), "=r"(r[2]), "=r"(r[3]) : "r"(a));
}
__device__ __forceinline__ void ldsm2(uint32_t* r, uint32_t a) {
    asm volatile("ldmatrix.sync.aligned.m8n8.x2.shared.b16 {%0,%1}, [%2];"
                 : "=r"(r[0]), "=r"(r[1]) : "r"(a));
}
__device__ __forceinline__ void mma_bf16(float* c, const uint32_t* a,
                                         const uint32_t* b) {
    asm volatile(
        "mma.sync.aligned.m16n8k16.row.col.f32.bf16.bf16.f32 "
        "{%0,%1,%2,%3}, {%4,%5,%6,%7}, {%8,%9}, {%0,%1,%2,%3};"
        : "+f"(c[0]), "+f"(c[1]), "+f"(c[2]), "+f"(c[3])
        : "r"(a[0]), "r"(a[1]), "r"(a[2]), "r"(a[3]), "r"(b[0]), "r"(b[1]));
}

__device__ __forceinline__ void split_bf16(float v, unsigned short& hi,
                                           unsigned short& lo) {
    __nv_bfloat16 h = __float2bfloat16(v);
    __nv_bfloat16 l = __float2bfloat16(v - __bfloat162float(h));
    hi = *(unsigned short*)&h;
    lo = *(unsigned short*)&l;
}

extern "C" __global__ void __launch_bounds__(256, 1) __cluster_dims__(8, 1, 1)
ctrnn_hmma(const float* __restrict__ x, const float* __restrict__ h0,
           const float* __restrict__ W_in, const float* __restrict__ b_in,
           const float* __restrict__ W_hh, float* __restrict__ out) {
    extern __shared__ char S[];
    const uint32_t sb = smem_u32(S);
    const int tid = threadIdx.x;
    const int warp = tid >> 5;          // n-strip (0..7): cols [warp*8, warp*8+8)
    const int lane = tid & 31;
    const int cid = blockIdx.x >> 3;    // cluster -> batch group (16 rows)
    const int rank = blockIdx.x & 7;    // -> column group (64 cols)
    const int rows0 = cid * 16;
    const int cols0 = rank * 64;

    // ---- one-time: W slice [64 cols x 640 k] -> smem bf16 hi/lo ----
    for (int i = tid; i < 64 * KTOT; i += 256) {
        int c = i / KTOT, k = i % KTOT;
        int gn = cols0 + c;
        float w = (k < NHID) ? W_hh[gn * NHID + k] : W_in[gn * INPUT + (k - NHID)];
        unsigned short hi, lo;
        split_bf16(w, hi, lo);
        *(unsigned short*)(S + S_WH + (c * APITCH + k) * 2) = hi;
        *(unsigned short*)(S + S_WL + (c * APITCH + k) * 2) = lo;
    }
    if (tid < 64) ((float*)(S + S_BIAS))[tid] = b_in[cols0 + tid];

    // ---- h0 -> h_old smem + exchange[0] (this CTA's 16x64 tile) ----
    {
        int r = tid >> 4, c = 4 * (tid & 15);
        float4 v = *(const float4*)&h0[(rows0 + r) * NHID + cols0 + c];
        float* hold = (float*)(S + S_HOLD);
        *(float4*)&hold[r * 64 + c] = v;
        unsigned short hh[4], hl[4];
        split_bf16(v.x, hh[0], hl[0]); split_bf16(v.y, hh[1], hl[1]);
        split_bf16(v.z, hh[2], hl[2]); split_bf16(v.w, hh[3], hl[3]);
        *(unsigned long long*)&g_hh[0][rows0 + r][cols0 + c] = *(unsigned long long*)hh;
        *(unsigned long long*)&g_hl[0][rows0 + r][cols0 + c] = *(unsigned long long*)hl;
    }
    // x_0: this CTA covers 16 rows x 16 x-cols
    {
        int r = tid >> 4, xc = tid & 15;
        float v = x[(rows0 + r) * INPUT + rank * 16 + xc];
        unsigned short hi, lo;
        split_bf16(v, hi, lo);
        *(unsigned short*)&g_hh[0][rows0 + r][NHID + rank * 16 + xc] = hi;
        *(unsigned short*)&g_hl[0][rows0 + r][NHID + rank * 16 + xc] = lo;
    }
    cluster_arrive();
    cluster_wait();

    // ---- ldmatrix lane address bases ----
    // A x4: lanes 0-7: rows 0-7 @k0 | 8-15: rows 8-15 @k0 | 16-23: rows 0-7 @k8
    //       | 24-31: rows 8-15 @k8  -> frags a0..a3 match m16n8k16 A layout.
    const int arow = lane & 15;
    const int akoff = (lane >> 4) ? 8 : 0;
    const uint32_t aH = sb + S_AH + (uint32_t)(arow * APITCH + akoff) * 2;
    const uint32_t aL = sb + S_AL + (uint32_t)(arow * APITCH + akoff) * 2;
    // B x2: lanes 0-7: cols strip*8+l @k0 | 8-15: same cols @k8 (lanes 16+ unused)
    const int bcol = warp * 8 + (lane & 7);
    const int bkoff = ((lane >> 3) & 1) ? 8 : 0;
    const uint32_t bH = sb + S_WH + (uint32_t)(bcol * APITCH + bkoff) * 2;
    const uint32_t bL = sb + S_WL + (uint32_t)(bcol * APITCH + bkoff) * 2;

    int p = 0;
    for (int t = 0; t < T_STEPS; t++) {
        // ---- stage A [16 x 640] hi/lo from L2 exchange into padded smem ----
        {
            int r = tid >> 4, seg = tid & 15;           // 40 cols = 80B per seg
            const uint4* srcH = (const uint4*)&g_hh[p][rows0 + r][seg * 40];
            const uint4* srcL = (const uint4*)&g_hl[p][rows0 + r][seg * 40];
            uint4* dstH = (uint4*)(S + S_AH + (r * APITCH + seg * 40) * 2);
            uint4* dstL = (uint4*)(S + S_AL + (r * APITCH + seg * 40) * 2);
#pragma unroll
            for (int j = 0; j < 5; j++) { dstH[j] = __ldcg(srcH + j); }
#pragma unroll
            for (int j = 0; j < 5; j++) { dstL[j] = __ldcg(srcL + j); }
        }
        // x_{t+1} prefetch (scalar; drains during GEMM)
        float xr = 0.0f;
        if (t + 1 < T_STEPS)
            xr = __ldcs(&x[(size_t)(t + 1) * BATCH * INPUT +
                           (size_t)(rows0 + (tid >> 4)) * INPUT + rank * 16 + (tid & 15)]);
        __syncthreads();

        // ---- GEMM: warp strip, 40 k-tiles x 3 split terms ----
        float acc[4] = {0.f, 0.f, 0.f, 0.f};
#pragma unroll 4
        for (int kt = 0; kt < 40; kt++) {
            uint32_t ah[4], al[4], bh[2], bl[2];
            uint32_t ko = (uint32_t)kt * 32;   // 16 bf16 = 32B per k-tile
            ldsm4(ah, aH + ko);
            ldsm4(al, aL + ko);
            ldsm2(bh, bH + ko);
            ldsm2(bl, bL + ko);
            mma_bf16(acc, ah, bh);
            mma_bf16(acc, ah, bl);
            mma_bf16(acc, al, bh);
        }

        // ---- epilogue: frag (r, r+8) x (n, n+1); bias+tanh+blend ----
        const int r0 = lane >> 2;
        const int n = warp * 8 + 2 * (lane & 3);
        float* hold = (float*)(S + S_HOLD);
        const float* bs = (const float*)(S + S_BIAS);
        float b0 = bs[n], b1 = bs[n + 1];
        float h00 = hold[r0 * 64 + n],       h01 = hold[r0 * 64 + n + 1];
        float h10 = hold[(r0 + 8) * 64 + n], h11 = hold[(r0 + 8) * 64 + n + 1];
        float v00 = h00 * 0.8f + 0.2f * tanhf(acc[0] + b0);
        float v01 = h01 * 0.8f + 0.2f * tanhf(acc[1] + b1);
        float v10 = h10 * 0.8f + 0.2f * tanhf(acc[2] + b0);
        float v11 = h11 * 0.8f + 0.2f * tanhf(acc[3] + b1);
        hold[r0 * 64 + n] = v00;       hold[r0 * 64 + n + 1] = v01;
        hold[(r0 + 8) * 64 + n] = v10; hold[(r0 + 8) * 64 + n + 1] = v11;

        // publish h_{t+1} hi/lo (bf16x2 per row-pair of cols)
        unsigned short s00h, s00l, s01h, s01l, s10h, s10l, s11h, s11l;
        split_bf16(v00, s00h, s00l); split_bf16(v01, s01h, s01l);
        split_bf16(v10, s10h, s10l); split_bf16(v11, s11h, s11l);
        *(uint32_t*)&g_hh[p ^ 1][rows0 + r0][cols0 + n] =
            (uint32_t)s00h | ((uint32_t)s01h << 16);
        *(uint32_t*)&g_hl[p ^ 1][rows0 + r0][cols0 + n] =
            (uint32_t)s00l | ((uint32_t)s01l << 16);
        *(uint32_t*)&g_hh[p ^ 1][rows0 + r0 + 8][cols0 + n] =
            (uint32_t)s10h | ((uint32_t)s11h << 16);
        *(uint32_t*)&g_hl[p ^ 1][rows0 + r0 + 8][cols0 + n] =
            (uint32_t)s10l | ((uint32_t)s11l << 16);
        // publish x_{t+1}
        if (t + 1 < T_STEPS) {
            unsigned short xh, xl;
            split_bf16(xr, xh, xl);
            *(unsigned short*)&g_hh[p ^ 1][rows0 + (tid >> 4)][NHID + rank * 16 + (tid & 15)] = xh;
            *(unsigned short*)&g_hl[p ^ 1][rows0 + (tid >> 4)][NHID + rank * 16 + (tid & 15)] = xl;
        }

        // release exchange stores; hide output stores inside the barrier
        cluster_arrive();
        {
            size_t ob = (size_t)t * BN + (size_t)(rows0 + r0) * NHID + cols0 + n;
            size_t ob8 = ob + 8 * NHID;
            *(float2*)&out[ob] = make_float2(v00, v01);
            *(float2*)&out[ob8] = make_float2(v10, v11);
            if (t == T_STEPS - 1) {
                *(float2*)&out[ob + (size_t)T_STEPS * BN - (size_t)t * BN] =
                    make_float2(v00, v01);
                *(float2*)&out[ob8 + (size_t)T_STEPS * BN - (size_t)t * BN] =
                    make_float2(v10, v11);
            }
        }
        cluster_wait();
        p ^= 1;
    }
}

extern "C" void kernel_launch(void* const* d_in, const int* in_sizes, int n_in,
                              void* d_out, int out_size) {
    const float* x    = (const float*)d_in[0];
    const float* h0   = (const float*)d_in[1];
    const float* W_in = (const float*)d_in[2];
    const float* b_in = (const float*)d_in[3];
    const float* W_hh = (const float*)d_in[4];
    float* out = (float*)d_out;

    cudaFuncSetAttribute(ctrnn_hmma,
                         cudaFuncAttributeMaxDynamicSharedMemorySize, SMEM_BYTES);
    ctrnn_hmma<<<128, 256, SMEM_BYTES>>>(x, h0, W_in, b_in, W_hh, out);
}